// round 10
// baseline (speedup 1.0000x reference)
#include <cuda_runtime.h>
#include <math.h>
#include <stdint.h>

// ---------------- problem constants ----------------
#define NN   2048
#define NT   512
#define BB   8
#define KK   4
#define CL   8                  // cluster size: 4 modes x {x,y}
#define NGRID (BB * CL)         // 64 CTAs
#define EN   (NN / CL)          // 256 elements per rank in epilogue gather
#define TWO_PI_F 6.283185307179586f

// output layout (flattened tuple, fp32)
#define OUT_EIF 0
#define OUT_XM  65536
#define OUT_YM  131072
#define OUT_BSX 196608
#define OUT_BSY 212992
#define OUT_LAM 229376
#define OUT_SC  245760

// block-wide reduce (u-projection only): 4 shuffles -> 32 partials -> 1 barrier
__device__ __forceinline__ float bred(float v, float* sred, int tid)
{
#pragma unroll
    for (int o = 8; o > 0; o >>= 1) v += __shfl_down_sync(0xffffffffu, v, o);
    if ((tid & 15) == 0) sred[tid >> 4] = v;
    __syncthreads();
    float s = 0.f;
#pragma unroll
    for (int j = 0; j < 8; j++) {
        float4 q = reinterpret_cast<float4*>(sred)[j];
        s += (q.x + q.y) + (q.z + q.w);
    }
    return s;
}

// interior 5-point stencil of (D^T D): [1,-4,6,-4,1]; w[k] = elem(base-2+k)
#define STEN5(w, c) ((w)[c] - 4.f*(w)[(c)+1] + 6.f*(w)[(c)+2] - 4.f*(w)[(c)+3] + (w)[(c)+4])

// Boundary rows, exact reference expressions, recomputed on edge threads only.
__device__ __forceinline__ void fix_bounds4(float coef, const float* d,
                                            const float* v, float* Av,
                                            bool isF, bool isL)
{
    if (isF) {
        Av[0] = coef * (2.f*v[0] - 3.f*v[1] + v[2]) + d[0]*v[0];
        Av[1] = coef * (-3.f*v[0] + 6.f*v[1] - 4.f*v[2] + v[3]) + d[1]*v[1];
    }
    if (isL) {
        Av[2] = coef * (v[0] - 4.f*v[1] + 6.f*v[2] - 3.f*v[3]) + d[2]*v[2];
        Av[3] = coef * (v[1] - 3.f*v[2] + 2.f*v[3]) + d[3]*v[3];
    }
}

// One-barrier-per-iteration CG.
//  - alpha uses EXACT rs: ||r_i||^2 partials are reduced at the NEXT epoch's
//    barrier (piggyback), so rs never carries formula error (R3 fix).
//  - beta uses rsF = rs - 2t*rA + t^2*AA (t = a*coef; dots on Ap/coef to avoid
//    fp32 overflow when coef ~ 2e10), clamped >= 0 (worst case: CG restart).
//  - break tests exact rs one epoch late, BEFORE that epoch's x update ==
//    reference freeze semantics.
//  - halos: neighbors' Ap edges published pre-barrier; each thread maintains
//    neighbor r/p halos by local recurrence (a, beta uniform). Parity
//    double-buffering (sp0/sp1, dot slots, pending slots) keeps one-barrier
//    epochs race-free.
// sred layout (floats): [dots parity0: 0..47 | dots parity1: 48..95 |
//                        pend parity0: 96..111 | pend parity1: 112..127]
__device__ __forceinline__ void cg_fast(int tid, float coef,
        const float* d, float* x, const float* rhs,
        float* sp0, float* sp1, float* sred, bool x0_zero)
{
    const int base = tid * 4;
    const int wid = tid >> 5, lane = tid & 31;
    const bool isF = (tid == 0), isL = (tid == NT - 1);
    const float inv_coef = 1.f / coef;
    float r[4], p[4];
    float rl = 0.f;

    __syncthreads();                       // prior readers of buffers done
    if (isF) {
        *reinterpret_cast<float2*>(sp0 - 2)  = make_float2(0.f, 0.f);
        *reinterpret_cast<float2*>(sp1 - 2)  = make_float2(0.f, 0.f);
    }
    if (isL) {
        *reinterpret_cast<float2*>(sp0 + NN) = make_float2(0.f, 0.f);
        *reinterpret_cast<float2*>(sp1 + NN) = make_float2(0.f, 0.f);
    }

    if (x0_zero) {
#pragma unroll
        for (int c = 0; c < 4; c++) { r[c] = rhs[c]; rl += r[c] * r[c]; }
    } else {
        *reinterpret_cast<float2*>(sp0 + base)     = make_float2(x[0], x[1]);
        *reinterpret_cast<float2*>(sp0 + base + 2) = make_float2(x[2], x[3]);
        __syncthreads();
        float2 L = *reinterpret_cast<const float2*>(sp0 + base - 2);
        float2 R = *reinterpret_cast<const float2*>(sp0 + base + 4);
        float w[8];
        w[0] = L.x; w[1] = L.y; w[6] = R.x; w[7] = R.y;
#pragma unroll
        for (int c = 0; c < 4; c++) w[c + 2] = x[c];
        float Ax[4];
#pragma unroll
        for (int c = 0; c < 4; c++) Ax[c] = coef * STEN5(w, c) + d[c] * x[c];
        fix_bounds4(coef, d, x, Ax, isF, isL);
#pragma unroll
        for (int c = 0; c < 4; c++) { r[c] = rhs[c] - Ax[c]; rl += r[c] * r[c]; }
        __syncthreads();     // x-halo reads done; sp0 free for epoch-0 Ap
    }
    // publish initial r halos to sp1 (epoch 0 uses sp0 for Ap); rs0 partial
    // into pending slot parity 1 (read by epoch 0).
    *reinterpret_cast<float2*>(sp1 + base)     = make_float2(r[0], r[1]);
    *reinterpret_cast<float2*>(sp1 + base + 2) = make_float2(r[2], r[3]);
    {
        float v = rl;
#pragma unroll
        for (int o = 16; o > 0; o >>= 1) v += __shfl_down_sync(0xffffffffu, v, o);
        if (lane == 0) sred[112 + wid] = v;
    }
    __syncthreads();
    float2 Li = *reinterpret_cast<const float2*>(sp1 + base - 2);
    float2 Ri = *reinterpret_cast<const float2*>(sp1 + base + 4);
    float hl0 = Li.x, hl1 = Li.y, hr0 = Ri.x, hr1 = Ri.y;   // neighbor r halos
    float ql0 = hl0, ql1 = hl1, qr0 = hr0, qr1 = hr1;       // neighbor p halos
#pragma unroll
    for (int c = 0; c < 4; c++) p[c] = r[c];

    for (int it = 0; it < 30; it++) {
        // ---- pre-barrier: stencil, publish Ap edges, 3-wide dot partials ----
        float w[8];
        w[0] = ql0; w[1] = ql1; w[6] = qr0; w[7] = qr1;
#pragma unroll
        for (int c = 0; c < 4; c++) w[c + 2] = p[c];
        float Ap[4], aps[4];
#pragma unroll
        for (int c = 0; c < 4; c++) Ap[c] = coef * STEN5(w, c) + d[c] * p[c];
        fix_bounds4(coef, d, p, Ap, isF, isL);
        float* spw = (it & 1) ? sp1 : sp0;
        *reinterpret_cast<float2*>(spw + base)     = make_float2(Ap[0], Ap[1]);
        *reinterpret_cast<float2*>(spw + base + 2) = make_float2(Ap[2], Ap[3]);
        float pA = 0.f, rA = 0.f, AAv = 0.f;
#pragma unroll
        for (int c = 0; c < 4; c++) {
            aps[c] = Ap[c] * inv_coef;
            pA  += p[c] * aps[c];
            rA  += r[c] * aps[c];
            AAv += aps[c] * aps[c];
        }
#pragma unroll
        for (int o = 16; o > 0; o >>= 1) {
            pA  += __shfl_down_sync(0xffffffffu, pA,  o);
            rA  += __shfl_down_sync(0xffffffffu, rA,  o);
            AAv += __shfl_down_sync(0xffffffffu, AAv, o);
        }
        float* db = sred + (it & 1) * 48;
        if (lane == 0) { db[wid] = pA; db[16 + wid] = rA; db[32 + wid] = AAv; }
        __syncthreads();                                   // THE barrier
        // ---- post-barrier: sum dots + pending exact rs ----
        const float* pb = sred + 96 + (((it + 1) & 1) << 4);
        float pA_t = 0.f, rA_t = 0.f, AA_t = 0.f, rs = 0.f;
#pragma unroll
        for (int j = 0; j < 4; j++) {
            float4 a4 = reinterpret_cast<const float4*>(db)[j];
            float4 b4 = reinterpret_cast<const float4*>(db + 16)[j];
            float4 c4 = reinterpret_cast<const float4*>(db + 32)[j];
            float4 e4 = reinterpret_cast<const float4*>(pb)[j];
            pA_t += (a4.x + a4.y) + (a4.z + a4.w);
            rA_t += (b4.x + b4.y) + (b4.z + b4.w);
            AA_t += (c4.x + c4.y) + (c4.z + c4.w);
            rs   += (e4.x + e4.y) + (e4.z + e4.w);
        }
        if (it > 0 && rs < 1e-12f) break;   // exact-rs break, pre-x-update ==
                                            // reference freeze (uniform)
        float pAp = coef * pA_t;
        float a = rs / (pAp + 1e-12f);
        float t = a * coef;
        float rsF = fmaxf(rs - 2.f * t * rA_t + t * t * AA_t, 0.f);
        float bta = rsF / (rs + 1e-12f);
        // neighbor halo recurrences (Ap edges from SMEM, a/bta uniform)
        float2 AL = *reinterpret_cast<const float2*>(spw + base - 2);
        float2 AR = *reinterpret_cast<const float2*>(spw + base + 4);
        hl0 -= a * AL.x; hl1 -= a * AL.y; hr0 -= a * AR.x; hr1 -= a * AR.y;
        ql0 = hl0 + bta * ql0; ql1 = hl1 + bta * ql1;
        qr0 = hr0 + bta * qr0; qr1 = hr1 + bta * qr1;
        // local updates + exact ||r_new||^2 partial (pending for next epoch)
        float rv = 0.f;
#pragma unroll
        for (int c = 0; c < 4; c++) {
            x[c] += a * p[c];
            r[c] -= a * Ap[c];
            rv += r[c] * r[c];
            p[c] = r[c] + bta * p[c];
        }
#pragma unroll
        for (int o = 16; o > 0; o >>= 1) rv += __shfl_down_sync(0xffffffffu, rv, o);
        if (lane == 0) sred[96 + ((it & 1) << 4) + wid] = rv;
    }
}

// fast phase scan on prefetched values: full block, 4 contiguous elems/thread.
__device__ __forceinline__ void fast_phase_v(float4 y4, float ym1, float halfdx,
                                             float* wsum, float ph4[4])
{
    int tid = threadIdx.x;
    int lane = tid & 31, wi = tid >> 5;
    float a0 = (tid > 0) ? (ym1 + y4.x) * halfdx : 0.f;
    float s0 = a0;
    float s1 = s0 + (y4.x + y4.y) * halfdx;
    float s2 = s1 + (y4.y + y4.z) * halfdx;
    float s3 = s2 + (y4.z + y4.w) * halfdx;
    float tot = s3, v = tot;
#pragma unroll
    for (int o = 1; o < 32; o <<= 1) {
        float n = __shfl_up_sync(0xffffffffu, v, o);
        if (lane >= o) v += n;
    }
    __syncthreads();                 // protect wsum reuse across calls
    if (lane == 31) wsum[wi] = v;
    __syncthreads();
    float off = 0.f;
    for (int j = 0; j < wi; j++) off += wsum[j];
    float excl = off + v - tot;
    ph4[0] = TWO_PI_F * (excl + s0);
    ph4[1] = TWO_PI_F * (excl + s1);
    ph4[2] = TWO_PI_F * (excl + s2);
    ph4[3] = TWO_PI_F * (excl + s3);
}

// DSMEM scalar load from cluster rank `rk`
__device__ __forceinline__ float dsmem_ldf(const float* ptr, int rk)
{
    uint32_t a = (uint32_t)__cvta_generic_to_shared(ptr);
    uint32_t ra; float v;
    asm volatile("mapa.shared::cluster.u32 %0, %1, %2;" : "=r"(ra) : "r"(a), "r"(rk));
    asm volatile("ld.shared::cluster.f32 %0, [%1];" : "=f"(v) : "r"(ra) : "memory");
    return v;
}

__device__ __forceinline__ void cluster_sync_()
{
    asm volatile("barrier.cluster.arrive.aligned;" ::: "memory");
    asm volatile("barrier.cluster.wait.aligned;"   ::: "memory");
}

// ====== ONE fused kernel: cluster of 8 CTAs = one batch (4 modes x {x,y}) ===
__global__ __launch_bounds__(NT, 1) __cluster_dims__(CL, 1, 1)
void fused_kernel(
    const float* __restrict__ s_in, const float* __restrict__ eIF,
    const float* __restrict__ xm, const float* __restrict__ ym,
    const float* __restrict__ sumx, const float* __restrict__ sumy,
    const float* __restrict__ lam, const int* __restrict__ mask,
    const float* __restrict__ initf,
    const float* __restrict__ alpha_p, const float* __restrict__ beta_p,
    const float* __restrict__ var_p, const float* __restrict__ fs_p,
    const int* __restrict__ iter_p,
    const float* __restrict__ fe_w1, const float* __restrict__ fe_b1,
    const float* __restrict__ fe_w2, const float* __restrict__ fe_b2,
    const float* __restrict__ pr_w1, const float* __restrict__ pr_b1,
    const float* __restrict__ pr_w2, const float* __restrict__ pr_b2,
    const float* __restrict__ pr_w3, const float* __restrict__ pr_b3,
    const float* __restrict__ iw_p,
    float* __restrict__ d_out)
{
    __shared__ __align__(16) float sraw0[NN + 8];  // CG parity buf 0 / contribution
    __shared__ __align__(16) float sraw1[NN + 8];  // CG parity buf 1 / new_eIF stash
    __shared__ __align__(16) float own[NN];        // own CG solution
    __shared__ __align__(16) float peer[NN];       // peer CG solution (DSMEM copy)
    __shared__ __align__(16) float u_buf[NN];
    __shared__ __align__(16) float sredX[128];
    __shared__ float wsum[16];
    __shared__ float m_avg[BB];
    __shared__ float m_h1[BB*32];
    __shared__ float m_z0[BB*18];
    __shared__ float m_z1[BB*64];
    __shared__ float m_z2[BB*32];
    __shared__ float m_res[BB*2];
    __shared__ float m_scal[4];

    float* const sbuf0 = sraw0 + 2;     // element-0 views, 2 guards each side
    float* const sbuf1 = sraw1 + 2;

    const int bkid = blockIdx.x;
    const int b     = bkid >> 3;        // batch
    const int rk    = bkid & 7;         // cluster rank
    const int kmode = rk >> 1;          // mode 0..3
    const int which = rk & 1;           // 0 = x-solve, 1 = y-solve
    const int tid = threadIdx.x;

    // ---------- prefetch all global inputs ----------
    const int base4 = tid * 4;
    const int bbase = b * NN + base4;
    const int mb    = (b * KK + kmode) * NN;       // this mode's row base
    const int rbase = mb + base4;
    const float alpha = *alpha_p, beta = *beta_p;
    const float varv = *var_p, fsv = *fs_p, iw = *iw_p;
    const int it_num = *iter_p;
    const bool act = (mask[b * KK + kmode] != 0);
    float4 sv   = *reinterpret_cast<const float4*>(s_in + bbase);
    float4 sx   = *reinterpret_cast<const float4*>(sumx + bbase);
    float4 sy   = *reinterpret_cast<const float4*>(sumy + bbase);
    float4 lv   = *reinterpret_cast<const float4*>(lam  + bbase);
    float4 eif4 = *reinterpret_cast<const float4*>(eIF  + rbase);
    float  eifm1 = (tid > 0) ? eIF[rbase - 1] : 0.f;
    float4 xm4  = *reinterpret_cast<const float4*>(xm + rbase);
    float4 ym4  = *reinterpret_cast<const float4*>(ym + rbase);
    float lamE = 0.f, sE = 0.f;
    const int giE = b * NN + rk * EN + (tid & (EN - 1));
    if (tid < EN) { lamE = lam[giE]; sE = s_in[giE]; }

    // ---------- MLP (recomputed per CTA; identical everywhere) ----------
    if (tid < BB) {
        const float* f = initf + tid * KK;
        m_avg[tid] = (((f[0] + f[1]) + f[2]) + f[3]) * 0.25f;
    }
    __syncthreads();
    if (tid < 256) {
        int bb = tid >> 5, j = tid & 31;
        m_h1[bb*32 + j] = fmaxf(0.f, m_avg[bb] * fe_w1[j] + fe_b1[j]);
    }
    __syncthreads();
    if (tid < 128) {
        int bb = tid >> 4, j = tid & 15;
        float acc = fe_b2[j];
        for (int e = 0; e < 32; e++) acc += m_h1[bb*32 + e] * fe_w2[j*32 + e];
        m_z0[bb*18 + j] = fmaxf(0.f, acc);
    }
    if (tid < BB) { m_z0[tid*18 + 16] = alpha; m_z0[tid*18 + 17] = beta; }
    __syncthreads();
    {
        int bb = tid >> 6, j = tid & 63;
        float acc = pr_b1[j];
        for (int e = 0; e < 18; e++) acc += m_z0[bb*18 + e] * pr_w1[j*18 + e];
        m_z1[bb*64 + j] = fmaxf(0.f, acc);
    }
    __syncthreads();
    if (tid < 256) {
        int bb = tid >> 5, j = tid & 31;
        float acc = pr_b2[j];
        for (int e = 0; e < 64; e++) acc += m_z1[bb*64 + e] * pr_w2[j*64 + e];
        m_z2[bb*32 + j] = fmaxf(0.f, acc);
    }
    __syncthreads();
    if (tid < 16) {
        int bb = tid >> 1, j = tid & 1;
        float acc = pr_b3[j];
        for (int e = 0; e < 32; e++) acc += m_z2[bb*32 + e] * pr_w3[j*32 + e];
        m_res[bb*2 + j] = tanhf(acc);
    }
    __syncthreads();
    if (tid == 0) {
        float fac = 1.f / (1.f + expf(-iw * (float)it_num));
        float m0 = 0.f, m1 = 0.f;
        for (int bb = 0; bb < BB; bb++) {
            m0 += (m_res[bb*2 + 0] * fac * 0.1f) * alpha;
            m1 += (m_res[bb*2 + 1] * fac * 0.1f) * beta;
        }
        m0 *= 0.125f; m1 *= 0.125f;
        float na = fminf(fmaxf(alpha + m0, 1e-6f), 0.01f);
        float nb = fminf(fmaxf(beta  + m1, 1e-6f), 0.1f);
        double bt = pow(10.0, (double)it_num / 36.0 - 10.0);
        float betathr = fminf((float)bt, nb);
        m_scal[0] = na; m_scal[1] = nb;
        m_scal[2] = 2.f / na; m_scal[3] = 2.f / betathr;
        if (bkid == 0) { d_out[OUT_SC + 0] = na; d_out[OUT_SC + 1] = nb; }
    }
    __syncthreads();
    const float na = m_scal[0];
    const float coefA = m_scal[2];
    const float coefS = m_scal[3];
    const float dxf = 1.0f / fsv;
    const float halfdx = 0.5f * dxf;

    // ---------- u = projec5(...) ----------
    float uv[4];
    uv[0] = sv.x - sx.x - sy.x - lv.x / na;
    uv[1] = sv.y - sx.y - sy.y - lv.y / na;
    uv[2] = sv.z - sx.z - sy.z - lv.z / na;
    uv[3] = sv.w - sx.w - sy.w - lv.w / na;
    {
        float loc = uv[0]*uv[0] + uv[1]*uv[1] + uv[2]*uv[2] + uv[3]*uv[3];
        float n2 = bred(loc, sredX, tid);
        float n = sqrtf(n2);
        float e = sqrtf((float)NN * varv);
        float scale = (n > e) ? (e / fmaxf(n, 1e-30f)) : 1.f;
#pragma unroll
        for (int c = 0; c < 4; c++) { uv[c] *= scale; u_buf[base4 + c] = uv[c]; }
    }

    // ---------- phase + rhs/diag/x0 (all in registers) ----------
    float d4[4], rhs4[4], x4[4];
    {
        float ph4[4];
        fast_phase_v(eif4, eifm1, halfdx, wsum, ph4);
#pragma unroll
        for (int c = 0; c < 4; c++) {
            float ssn, ccs;
            sincosf(ph4[c], &ssn, &ccs);
            float xv = ((const float*)&xm4.x)[c];
            float yv = ((const float*)&ym4.x)[c];
            float resid = ((const float*)&sv.x)[c]
                        - (((const float*)&sx.x)[c] - xv * ccs)
                        - (((const float*)&sy.x)[c] - yv * ssn)
                        - uv[c]
                        - ((const float*)&lv.x)[c] / na;
            float t = which ? ssn : ccs;
            d4[c] = t * t + 1e-6f;
            rhs4[c] = t * resid;
            x4[c] = which ? yv : xv;
        }
    }

    // ---------- this CTA's CG solve (x OR y system) ----------
    cg_fast(tid, coefA, d4, x4, rhs4, sbuf0, sbuf1, sredX, false);
    __syncthreads();       // CG trailing SMEM traffic complete
#pragma unroll
    for (int c = 0; c < 4; c++) own[base4 + c] = x4[c];
    __syncthreads();

    // ---------- exchange with paired CTA (rank ^ 1) via DSMEM ----------
    cluster_sync_();
    {
        const int prk = rk ^ 1;
#pragma unroll
        for (int c = 0; c < 4; c++)
            peer[base4 + c] = dsmem_ldf(&own[base4 + c], prk);
    }
    const float* xsP = which ? peer : own;
    const float* ysP = which ? own : peer;

    // ---------- deltaIF + smooth CG (duplicated across the pair) ----------
    float sx4[4];
    {
        float srhs[4], sd[4];
        __syncthreads();       // peer[] fully written before neighbor reads
#pragma unroll
        for (int c = 0; c < 4; c++) {
            int i = base4 + c;
            float xb, yb;
            if (i == 0) {
                xb = (xsP[1] - xsP[0]) / dxf;
                yb = (ysP[1] - ysP[0]) / dxf;
            } else if (i == NN - 1) {
                xb = (xsP[NN-1] - xsP[NN-2]) / dxf;
                yb = (ysP[NN-1] - ysP[NN-2]) / dxf;
            } else {
                xb = (xsP[i+1] - xsP[i-1]) / (2.0f * dxf);
                yb = (ysP[i+1] - ysP[i-1]) / (2.0f * dxf);
            }
            float xv = xsP[i], yv = ysP[i];
            float denom = xv * xv + yv * yv + 1e-12f;
            srhs[c] = (xv * yb - yv * xb) / (denom * TWO_PI_F);
            sd[c] = 1.0f + 1e-6f;
            sx4[c] = 0.f;
        }
        cg_fast(tid, coefS, sd, sx4, srhs, sbuf0, sbuf1, sredX, true);
        __syncthreads();   // CG trailing SMEM traffic complete before reuse
    }

    // ---------- outputs eIF/xm(/ym) + stash new_eIF ----------
    float ne4[4];
#pragma unroll
    for (int c = 0; c < 4; c++) {
        int i = base4 + c;
        int gi = mb + i;
        float e = ((const float*)&eif4.x)[c];
        ne4[c] = act ? (e - 0.5f * sx4[c]) : e;
        if (which == 0) {
            d_out[OUT_EIF + gi] = ne4[c];
            d_out[OUT_XM  + gi] = act ? xsP[i] : ((const float*)&xm4.x)[c];
        } else {
            d_out[OUT_YM  + gi] = act ? ysP[i] : ((const float*)&ym4.x)[c];
        }
        sbuf1[i] = ne4[c];
    }
    __syncthreads();

    // ---------- new phase + masked contribution into sbuf0 ----------
    {
        float nem1 = (tid > 0) ? sbuf1[base4 - 1] : 0.f;
        float4 ne = make_float4(ne4[0], ne4[1], ne4[2], ne4[3]);
        float ph4[4];
        fast_phase_v(ne, nem1, halfdx, wsum, ph4);
        float cc[4];
#pragma unroll
        for (int c = 0; c < 4; c++) {
            float ssn, ccs;
            sincosf(ph4[c], &ssn, &ccs);
            int i = base4 + c;
            cc[c] = act ? (which ? ysP[i] * ssn : xsP[i] * ccs) : 0.f;
        }
        __syncthreads();
#pragma unroll
        for (int c = 0; c < 4; c++) sbuf0[base4 + c] = cc[c];
    }

    // ---------- cluster gather: bsx/bsy + lamuda ----------
    cluster_sync_();
    if (tid < EN) {
        int i = rk * EN + tid;
        float bsx = 0.f, bsy = 0.f;
#pragma unroll
        for (int k = 0; k < KK; k++) {
            bsx += dsmem_ldf(&sbuf0[i], 2 * k);
            bsy += dsmem_ldf(&sbuf0[i], 2 * k + 1);
        }
        d_out[OUT_BSX + giE] = bsx;
        d_out[OUT_BSY + giE] = bsy;
        d_out[OUT_LAM + giE] = lamE + na * (u_buf[i] + bsx + bsy - sE);
    }
    cluster_sync_();
}

// ---------------- launch ---------------------------------------------------
extern "C" void kernel_launch(void* const* d_in, const int* in_sizes, int n_in,
                              void* d_out_v, int out_size)
{
    const float* s      = (const float*)d_in[0];
    const float* eIF    = (const float*)d_in[1];
    const float* xm     = (const float*)d_in[2];
    const float* ym     = (const float*)d_in[3];
    const float* sum_x  = (const float*)d_in[4];
    const float* sum_y  = (const float*)d_in[5];
    const float* lamuda = (const float*)d_in[6];
    const float* initf  = (const float*)d_in[7];
    const int*   mmask  = (const int*)  d_in[8];
    const float* alpha  = (const float*)d_in[9];
    const float* beta   = (const float*)d_in[10];
    const float* var    = (const float*)d_in[11];
    const float* fs     = (const float*)d_in[12];
    const int*   iter   = (const int*)  d_in[13];
    const float* fe_w1  = (const float*)d_in[14];
    const float* fe_b1  = (const float*)d_in[15];
    const float* fe_w2  = (const float*)d_in[16];
    const float* fe_b2  = (const float*)d_in[17];
    const float* pr_w1  = (const float*)d_in[18];
    const float* pr_b1  = (const float*)d_in[19];
    const float* pr_w2  = (const float*)d_in[20];
    const float* pr_b2  = (const float*)d_in[21];
    const float* pr_w3  = (const float*)d_in[22];
    const float* pr_b3  = (const float*)d_in[23];
    const float* iw     = (const float*)d_in[24];
    float* d_out = (float*)d_out_v;

    fused_kernel<<<NGRID, NT>>>(s, eIF, xm, ym, sum_x, sum_y, lamuda, mmask,
                                initf, alpha, beta, var, fs, iter,
                                fe_w1, fe_b1, fe_w2, fe_b2,
                                pr_w1, pr_b1, pr_w2, pr_b2, pr_w3, pr_b3,
                                iw, d_out);
}

// round 11
// speedup vs baseline: 1.2735x; 1.2735x over previous
#include <cuda_runtime.h>
#include <math.h>
#include <stdint.h>

// ---------------- problem constants ----------------
#define NN   2048
#define NT   128                // threads per CTA
#define NPT  16                 // elements per thread (NN/NT)
#define BB   8
#define KK   4
#define CL   8                  // cluster size: 4 modes x {x,y}
#define NGRID (BB * CL)         // 64 CTAs
#define EN   (NN / CL)          // 256 elements per rank in epilogue gather
#define TWO_PI_F 6.283185307179586f

// output layout (flattened tuple, fp32)
#define OUT_EIF 0
#define OUT_XM  65536
#define OUT_YM  131072
#define OUT_BSX 196608
#define OUT_BSY 212992
#define OUT_LAM 229376
#define OUT_SC  245760

// block reduce over 128 threads: 3 shuffles (8-lane groups) -> 16 partials ->
// 1 barrier -> every thread sums 4x float4.
__device__ __forceinline__ float bred(float v, float* sred, int tid)
{
#pragma unroll
    for (int o = 4; o > 0; o >>= 1) v += __shfl_down_sync(0xffffffffu, v, o);
    if ((tid & 7) == 0) sred[tid >> 3] = v;
    __syncthreads();
    float4 q0 = reinterpret_cast<float4*>(sred)[0];
    float4 q1 = reinterpret_cast<float4*>(sred)[1];
    float4 q2 = reinterpret_cast<float4*>(sred)[2];
    float4 q3 = reinterpret_cast<float4*>(sred)[3];
    float s0 = (q0.x + q0.y) + (q0.z + q0.w);
    float s1 = (q1.x + q1.y) + (q1.z + q1.w);
    float s2 = (q2.x + q2.y) + (q2.z + q2.w);
    float s3 = (q3.x + q3.y) + (q3.z + q3.w);
    return (s0 + s1) + (s2 + s3);
}

// interior 5-point stencil of (D^T D): [1,-4,6,-4,1]; w[k] = elem(base-2+k)
#define STEN5(w, c) ((w)[c] - 4.f*(w)[(c)+1] + 6.f*(w)[(c)+2] - 4.f*(w)[(c)+3] + (w)[(c)+4])

// Boundary rows, exact reference expressions, recomputed on edge threads only.
__device__ __forceinline__ void fix_bounds(float coef, const float* d,
                                           const float* v, float* Av,
                                           bool isF, bool isL)
{
    if (isF) {
        Av[0] = coef * (2.f*v[0] - 3.f*v[1] + v[2]) + d[0]*v[0];
        Av[1] = coef * (-3.f*v[0] + 6.f*v[1] - 4.f*v[2] + v[3]) + d[1]*v[1];
    }
    if (isL) {
        Av[NPT-2] = coef * (v[NPT-4] - 4.f*v[NPT-3] + 6.f*v[NPT-2] - 3.f*v[NPT-1])
                  + d[NPT-2]*v[NPT-2];
        Av[NPT-1] = coef * (v[NPT-3] - 3.f*v[NPT-2] + 2.f*v[NPT-1])
                  + d[NPT-1]*v[NPT-1];
    }
}

// 128-thread CG, NPT=16, reference semantics: explicit rsnew = ||r-a*Ap||^2,
// freeze == break. p in registers; r halos via SMEM float2; neighbor p halos
// reconstructed as r_halo + beta*p_halo_old. sp = element-0 view with 2 guard
// floats each side (zeroed; never used by boundary math). 2 barriers/iter.
__device__ __forceinline__ void cg_solve(int tid, float coef,
        const float* d, float* x, const float* rhs,
        float* sp, float* sA, float* sB, bool x0_zero)
{
    const int base = tid * NPT;
    const bool isF = (tid == 0);
    const bool isL = (tid == NT - 1);
    float r[NPT], p[NPT];
    float rl = 0.f;

    __syncthreads();                       // prior readers of sp region done
    if (isF) *reinterpret_cast<float2*>(sp - 2)  = make_float2(0.f, 0.f);
    if (isL) *reinterpret_cast<float2*>(sp + NN) = make_float2(0.f, 0.f);

    if (x0_zero) {
#pragma unroll
        for (int c = 0; c < NPT; c++) { r[c] = rhs[c]; rl += r[c] * r[c]; }
    } else {
        *reinterpret_cast<float2*>(sp + base)           = make_float2(x[0], x[1]);
        *reinterpret_cast<float2*>(sp + base + NPT - 2) = make_float2(x[NPT-2], x[NPT-1]);
        __syncthreads();
        float2 L = *reinterpret_cast<const float2*>(sp + base - 2);
        float2 R = *reinterpret_cast<const float2*>(sp + base + NPT);
        float w[NPT + 4];
        w[0] = L.x; w[1] = L.y; w[NPT+2] = R.x; w[NPT+3] = R.y;
#pragma unroll
        for (int c = 0; c < NPT; c++) w[c + 2] = x[c];
        float Ax[NPT];
#pragma unroll
        for (int c = 0; c < NPT; c++) Ax[c] = coef * STEN5(w, c) + d[c] * x[c];
        fix_bounds(coef, d, x, Ax, isF, isL);
#pragma unroll
        for (int c = 0; c < NPT; c++) { r[c] = rhs[c] - Ax[c]; rl += r[c] * r[c]; }
        __syncthreads();                   // x-halo reads done before overwrite
    }
    *reinterpret_cast<float2*>(sp + base)           = make_float2(r[0], r[1]);
    *reinterpret_cast<float2*>(sp + base + NPT - 2) = make_float2(r[NPT-2], r[NPT-1]);
    float rs = bred(rl, sB, tid);
    float2 Li = *reinterpret_cast<const float2*>(sp + base - 2);
    float2 Ri = *reinterpret_cast<const float2*>(sp + base + NPT);
    float hl0 = Li.x, hl1 = Li.y, hr0 = Ri.x, hr1 = Ri.y;
#pragma unroll
    for (int c = 0; c < NPT; c++) p[c] = r[c];

    for (int it = 0; it < 30; it++) {
        float w[NPT + 4];
        w[0] = hl0; w[1] = hl1; w[NPT+2] = hr0; w[NPT+3] = hr1;
#pragma unroll
        for (int c = 0; c < NPT; c++) w[c + 2] = p[c];
        float Ap[NPT];
#pragma unroll
        for (int c = 0; c < NPT; c++) Ap[c] = coef * STEN5(w, c) + d[c] * p[c];
        fix_bounds(coef, d, p, Ap, isF, isL);
        float pl = 0.f;
#pragma unroll
        for (int c = 0; c < NPT; c++) pl += p[c] * Ap[c];
        float pAp = bred(pl, sA, tid);                          // barrier 1
        float a = rs / (pAp + 1e-12f);
        float rl2 = 0.f;
#pragma unroll
        for (int c = 0; c < NPT; c++) { r[c] -= a * Ap[c]; rl2 += r[c] * r[c]; }
        *reinterpret_cast<float2*>(sp + base)           = make_float2(r[0], r[1]);
        *reinterpret_cast<float2*>(sp + base + NPT - 2) = make_float2(r[NPT-2], r[NPT-1]);
        float rsnew = bred(rl2, sB, tid);                       // barrier 2
#pragma unroll
        for (int c = 0; c < NPT; c++) x[c] += a * p[c];         // hidden by LDS
        if (rsnew < 1e-12f) break;          // == sqrt(rsnew) < 1e-6 (freeze)
        float bta = rsnew / (rs + 1e-12f);
        float2 Ln = *reinterpret_cast<const float2*>(sp + base - 2);
        float2 Rn = *reinterpret_cast<const float2*>(sp + base + NPT);
#pragma unroll
        for (int c = 0; c < NPT; c++) p[c] = r[c] + bta * p[c];
        hl0 = Ln.x + bta * hl0; hl1 = Ln.y + bta * hl1;
        hr0 = Rn.x + bta * hr0; hr1 = Rn.y + bta * hr1;
        rs = rsnew;
    }
}

// phase scan: 128 threads x 16 contiguous elems (in registers). ym1 = element
// before this thread's chunk (ignored for tid 0). Output ph[c] = 2pi*cumtrapz.
__device__ __forceinline__ void fast_phase(const float* y, float ym1, float halfdx,
                                           float* wsum, float* ph)
{
    int tid = threadIdx.x;
    int lane = tid & 31, wi = tid >> 5;
    float prev = ym1;
    float acc = 0.f;
#pragma unroll
    for (int c = 0; c < NPT; c++) {
        float a = (prev + y[c]) * halfdx;
        if (c == 0 && tid == 0) a = 0.f;
        acc += a;
        ph[c] = acc;
        prev = y[c];
    }
    float tot = acc, v = tot;
#pragma unroll
    for (int o = 1; o < 32; o <<= 1) {
        float n = __shfl_up_sync(0xffffffffu, v, o);
        if (lane >= o) v += n;
    }
    __syncthreads();                 // protect wsum reuse across calls
    if (lane == 31) wsum[wi] = v;
    __syncthreads();
    float off = 0.f;
    for (int j = 0; j < wi; j++) off += wsum[j];
    float excl = off + v - tot;
#pragma unroll
    for (int c = 0; c < NPT; c++) ph[c] = TWO_PI_F * (excl + ph[c]);
}

// DSMEM scalar load from cluster rank `rk`
__device__ __forceinline__ float dsmem_ldf(const float* ptr, int rk)
{
    uint32_t a = (uint32_t)__cvta_generic_to_shared(ptr);
    uint32_t ra; float v;
    asm volatile("mapa.shared::cluster.u32 %0, %1, %2;" : "=r"(ra) : "r"(a), "r"(rk));
    asm volatile("ld.shared::cluster.f32 %0, [%1];" : "=f"(v) : "r"(ra) : "memory");
    return v;
}

__device__ __forceinline__ void cluster_sync_()
{
    asm volatile("barrier.cluster.arrive.aligned;" ::: "memory");
    asm volatile("barrier.cluster.wait.aligned;"   ::: "memory");
}

// ====== ONE fused kernel: cluster of 8 CTAs = one batch (4 modes x {x,y}) ===
__global__ __launch_bounds__(NT, 1) __cluster_dims__(CL, 1, 1)
void fused_kernel(
    const float* __restrict__ s_in, const float* __restrict__ eIF,
    const float* __restrict__ xm, const float* __restrict__ ym,
    const float* __restrict__ sumx, const float* __restrict__ sumy,
    const float* __restrict__ lam, const int* __restrict__ mask,
    const float* __restrict__ initf,
    const float* __restrict__ alpha_p, const float* __restrict__ beta_p,
    const float* __restrict__ var_p, const float* __restrict__ fs_p,
    const int* __restrict__ iter_p,
    const float* __restrict__ fe_w1, const float* __restrict__ fe_b1,
    const float* __restrict__ fe_w2, const float* __restrict__ fe_b2,
    const float* __restrict__ pr_w1, const float* __restrict__ pr_b1,
    const float* __restrict__ pr_w2, const float* __restrict__ pr_b2,
    const float* __restrict__ pr_w3, const float* __restrict__ pr_b3,
    const float* __restrict__ iw_p,
    float* __restrict__ d_out)
{
    __shared__ __align__(16) float sraw0[NN + 8];  // CG workspace / contribution
    __shared__ __align__(16) float sraw1[NN + 8];  // new_eIF stash
    __shared__ __align__(16) float own[NN];        // own CG solution
    __shared__ __align__(16) float peer[NN];       // peer CG solution (DSMEM copy)
    __shared__ __align__(16) float u_buf[NN];
    __shared__ __align__(16) float sredA[16];
    __shared__ __align__(16) float sredB[16];
    __shared__ float wsum[4];
    __shared__ float m_avg[BB];
    __shared__ float m_h1[BB*32];
    __shared__ float m_z0[BB*18];
    __shared__ float m_z1[BB*64];
    __shared__ float m_z2[BB*32];
    __shared__ float m_res[BB*2];
    __shared__ float m_scal[4];

    float* const sbuf0 = sraw0 + 2;     // element-0 views, 2 guards each side
    float* const sbuf1 = sraw1 + 2;

    const int bkid = blockIdx.x;
    const int b     = bkid >> 3;        // batch
    const int rk    = bkid & 7;         // cluster rank
    const int kmode = rk >> 1;          // mode 0..3
    const int which = rk & 1;           // 0 = x-solve, 1 = y-solve
    const int tid = threadIdx.x;

    const int base16 = tid * NPT;
    const int bbase = b * NN + base16;
    const int mb    = (b * KK + kmode) * NN;       // this mode's row base
    const int rbase = mb + base16;
    const float alpha = *alpha_p, beta = *beta_p;
    const float varv = *var_p, fsv = *fs_p, iw = *iw_p;
    const int it_num = *iter_p;
    const bool act = (mask[b * KK + kmode] != 0);
    // epilogue gather prefetch (2 elements per thread)
    const int giE0 = b * NN + rk * EN + tid;
    const int giE1 = giE0 + NT;
    const float lamE0 = lam[giE0], lamE1 = lam[giE1];
    const float sE0 = s_in[giE0],  sE1 = s_in[giE1];

    // ---------- MLP (recomputed per CTA; identical everywhere) ----------
    if (tid < BB) {
        const float* f = initf + tid * KK;
        m_avg[tid] = (((f[0] + f[1]) + f[2]) + f[3]) * 0.25f;
    }
    __syncthreads();
#pragma unroll
    for (int o = 0; o < 2; o++) {       // fe1: 256 outputs
        int idx = tid + o * NT;
        int bb = idx >> 5, j = idx & 31;
        m_h1[bb*32 + j] = fmaxf(0.f, m_avg[bb] * fe_w1[j] + fe_b1[j]);
    }
    __syncthreads();
    {                                    // fe2: 128 outputs
        int bb = tid >> 4, j = tid & 15;
        float acc = fe_b2[j];
        for (int e = 0; e < 32; e++) acc += m_h1[bb*32 + e] * fe_w2[j*32 + e];
        m_z0[bb*18 + j] = fmaxf(0.f, acc);
    }
    if (tid < BB) { m_z0[tid*18 + 16] = alpha; m_z0[tid*18 + 17] = beta; }
    __syncthreads();
#pragma unroll
    for (int o = 0; o < 4; o++) {       // pr1: 512 outputs
        int idx = tid + o * NT;
        int bb = idx >> 6, j = idx & 63;
        float acc = pr_b1[j];
        for (int e = 0; e < 18; e++) acc += m_z0[bb*18 + e] * pr_w1[j*18 + e];
        m_z1[bb*64 + j] = fmaxf(0.f, acc);
    }
    __syncthreads();
#pragma unroll
    for (int o = 0; o < 2; o++) {       // pr2: 256 outputs
        int idx = tid + o * NT;
        int bb = idx >> 5, j = idx & 31;
        float acc = pr_b2[j];
        for (int e = 0; e < 64; e++) acc += m_z1[bb*64 + e] * pr_w2[j*64 + e];
        m_z2[bb*32 + j] = fmaxf(0.f, acc);
    }
    __syncthreads();
    if (tid < 16) {                      // pr3: 16 outputs
        int bb = tid >> 1, j = tid & 1;
        float acc = pr_b3[j];
        for (int e = 0; e < 32; e++) acc += m_z2[bb*32 + e] * pr_w3[j*32 + e];
        m_res[bb*2 + j] = tanhf(acc);
    }
    __syncthreads();
    if (tid == 0) {
        float fac = 1.f / (1.f + expf(-iw * (float)it_num));
        float m0 = 0.f, m1 = 0.f;
        for (int bb = 0; bb < BB; bb++) {
            m0 += (m_res[bb*2 + 0] * fac * 0.1f) * alpha;
            m1 += (m_res[bb*2 + 1] * fac * 0.1f) * beta;
        }
        m0 *= 0.125f; m1 *= 0.125f;
        float na = fminf(fmaxf(alpha + m0, 1e-6f), 0.01f);
        float nb = fminf(fmaxf(beta  + m1, 1e-6f), 0.1f);
        double bt = pow(10.0, (double)it_num / 36.0 - 10.0);
        float betathr = fminf((float)bt, nb);
        m_scal[0] = na; m_scal[1] = nb;
        m_scal[2] = 2.f / na; m_scal[3] = 2.f / betathr;
        if (bkid == 0) { d_out[OUT_SC + 0] = na; d_out[OUT_SC + 1] = nb; }
    }
    __syncthreads();
    const float na = m_scal[0];
    const float coefA = m_scal[2];
    const float coefS = m_scal[3];
    const float dxf = 1.0f / fsv;
    const float halfdx = 0.5f * dxf;

    // ---------- u = projec5(...) ----------
    {
        float loc = 0.f;
        float v16[NPT];
#pragma unroll
        for (int q = 0; q < NPT/4; q++) {
            float4 a = *reinterpret_cast<const float4*>(s_in + bbase + 4*q);
            float4 bq = *reinterpret_cast<const float4*>(sumx + bbase + 4*q);
            float4 cq = *reinterpret_cast<const float4*>(sumy + bbase + 4*q);
            float4 eq = *reinterpret_cast<const float4*>(lam  + bbase + 4*q);
            float t0 = a.x - bq.x - cq.x - eq.x / na;
            float t1 = a.y - bq.y - cq.y - eq.y / na;
            float t2 = a.z - bq.z - cq.z - eq.z / na;
            float t3 = a.w - bq.w - cq.w - eq.w / na;
            v16[4*q+0] = t0; v16[4*q+1] = t1; v16[4*q+2] = t2; v16[4*q+3] = t3;
            loc += t0*t0 + t1*t1 + t2*t2 + t3*t3;
        }
        float n2 = bred(loc, sredA, tid);
        float n = sqrtf(n2);
        float e = sqrtf((float)NN * varv);
        float scale = (n > e) ? (e / fmaxf(n, 1e-30f)) : 1.f;
#pragma unroll
        for (int c = 0; c < NPT; c++) u_buf[base16 + c] = v16[c] * scale;
    }

    // ---------- phase + rhs/diag/x0 (registers) ----------
    float d16[NPT], rhs16[NPT], x16[NPT];
    {
        float eifr[NPT];
#pragma unroll
        for (int q = 0; q < NPT/4; q++) {
            float4 t = *reinterpret_cast<const float4*>(eIF + rbase + 4*q);
            eifr[4*q+0] = t.x; eifr[4*q+1] = t.y; eifr[4*q+2] = t.z; eifr[4*q+3] = t.w;
        }
        float eifm1 = (tid > 0) ? eIF[rbase - 1] : 0.f;
        float ph[NPT];
        fast_phase(eifr, eifm1, halfdx, wsum, ph);
#pragma unroll
        for (int q = 0; q < NPT/4; q++) {
            float4 a = *reinterpret_cast<const float4*>(s_in + bbase + 4*q);
            float4 bq = *reinterpret_cast<const float4*>(sumx + bbase + 4*q);
            float4 cq = *reinterpret_cast<const float4*>(sumy + bbase + 4*q);
            float4 eq = *reinterpret_cast<const float4*>(lam  + bbase + 4*q);
            float4 xq = *reinterpret_cast<const float4*>(xm + rbase + 4*q);
            float4 yq = *reinterpret_cast<const float4*>(ym + rbase + 4*q);
#pragma unroll
            for (int j = 0; j < 4; j++) {
                int c = 4*q + j;
                float ssn, ccs;
                sincosf(ph[c], &ssn, &ccs);
                float xv = ((const float*)&xq.x)[j];
                float yv = ((const float*)&yq.x)[j];
                float resid = ((const float*)&a.x)[j]
                            - (((const float*)&bq.x)[j] - xv * ccs)
                            - (((const float*)&cq.x)[j] - yv * ssn)
                            - u_buf[base16 + c]
                            - ((const float*)&eq.x)[j] / na;
                float t = which ? ssn : ccs;
                d16[c] = t * t + 1e-6f;
                rhs16[c] = t * resid;
                x16[c] = which ? yv : xv;
            }
        }
    }

    // ---------- this CTA's CG solve (x OR y system) ----------
    cg_solve(tid, coefA, d16, x16, rhs16, sbuf0, sredA, sredB, false);
    __syncthreads();       // CG trailing SMEM traffic complete
#pragma unroll
    for (int c = 0; c < NPT; c++) own[base16 + c] = x16[c];
    __syncthreads();

    // ---------- exchange with paired CTA (rank ^ 1) via DSMEM ----------
    cluster_sync_();
    {
        const int prk = rk ^ 1;
#pragma unroll
        for (int c = 0; c < NPT; c++)
            peer[base16 + c] = dsmem_ldf(&own[base16 + c], prk);
    }
    const float* xsP = which ? peer : own;
    const float* ysP = which ? own : peer;

    // ---------- deltaIF + smooth CG (duplicated across the pair) ----------
    float sx16[NPT];
    {
        float srhs[NPT], sd[NPT];
        __syncthreads();       // peer[] fully written before neighbor reads
#pragma unroll
        for (int c = 0; c < NPT; c++) {
            int i = base16 + c;
            float xb, yb;
            if (i == 0) {
                xb = (xsP[1] - xsP[0]) / dxf;
                yb = (ysP[1] - ysP[0]) / dxf;
            } else if (i == NN - 1) {
                xb = (xsP[NN-1] - xsP[NN-2]) / dxf;
                yb = (ysP[NN-1] - ysP[NN-2]) / dxf;
            } else {
                xb = (xsP[i+1] - xsP[i-1]) / (2.0f * dxf);
                yb = (ysP[i+1] - ysP[i-1]) / (2.0f * dxf);
            }
            float xv = xsP[i], yv = ysP[i];
            float denom = xv * xv + yv * yv + 1e-12f;
            srhs[c] = (xv * yb - yv * xb) / (denom * TWO_PI_F);
            sd[c] = 1.0f + 1e-6f;
            sx16[c] = 0.f;
        }
        cg_solve(tid, coefS, sd, sx16, srhs, sbuf0, sredA, sredB, true);
        __syncthreads();   // CG trailing SMEM traffic complete before reuse
    }

    // ---------- outputs eIF/xm(/ym) + stash new_eIF ----------
    float ne16[NPT];
#pragma unroll
    for (int c = 0; c < NPT; c++) {
        int i = base16 + c;
        int gi = mb + i;
        float e = eIF[gi];
        ne16[c] = act ? (e - 0.5f * sx16[c]) : e;
        if (which == 0) {
            d_out[OUT_EIF + gi] = ne16[c];
            d_out[OUT_XM  + gi] = act ? xsP[i] : xm[gi];
        } else {
            d_out[OUT_YM  + gi] = act ? ysP[i] : ym[gi];
        }
        sbuf1[i] = ne16[c];
    }
    __syncthreads();

    // ---------- new phase + masked contribution into sbuf0 ----------
    {
        float nem1 = (tid > 0) ? sbuf1[base16 - 1] : 0.f;
        float ph[NPT];
        fast_phase(ne16, nem1, halfdx, wsum, ph);
        float cc[NPT];
#pragma unroll
        for (int c = 0; c < NPT; c++) {
            float ssn, ccs;
            sincosf(ph[c], &ssn, &ccs);
            int i = base16 + c;
            cc[c] = act ? (which ? ysP[i] * ssn : xsP[i] * ccs) : 0.f;
        }
        __syncthreads();
#pragma unroll
        for (int c = 0; c < NPT; c++) sbuf0[base16 + c] = cc[c];
    }

    // ---------- cluster gather: bsx/bsy + lamuda ----------
    cluster_sync_();
    {
        int i0 = rk * EN + tid;
        int i1 = i0 + NT;
        float bsx0 = 0.f, bsy0 = 0.f, bsx1 = 0.f, bsy1 = 0.f;
#pragma unroll
        for (int k = 0; k < KK; k++) {
            bsx0 += dsmem_ldf(&sbuf0[i0], 2 * k);
            bsy0 += dsmem_ldf(&sbuf0[i0], 2 * k + 1);
            bsx1 += dsmem_ldf(&sbuf0[i1], 2 * k);
            bsy1 += dsmem_ldf(&sbuf0[i1], 2 * k + 1);
        }
        d_out[OUT_BSX + giE0] = bsx0;
        d_out[OUT_BSY + giE0] = bsy0;
        d_out[OUT_LAM + giE0] = lamE0 + na * (u_buf[i0] + bsx0 + bsy0 - sE0);
        d_out[OUT_BSX + giE1] = bsx1;
        d_out[OUT_BSY + giE1] = bsy1;
        d_out[OUT_LAM + giE1] = lamE1 + na * (u_buf[i1] + bsx1 + bsy1 - sE1);
    }
    cluster_sync_();
}

// ---------------- launch ---------------------------------------------------
extern "C" void kernel_launch(void* const* d_in, const int* in_sizes, int n_in,
                              void* d_out_v, int out_size)
{
    const float* s      = (const float*)d_in[0];
    const float* eIF    = (const float*)d_in[1];
    const float* xm     = (const float*)d_in[2];
    const float* ym     = (const float*)d_in[3];
    const float* sum_x  = (const float*)d_in[4];
    const float* sum_y  = (const float*)d_in[5];
    const float* lamuda = (const float*)d_in[6];
    const float* initf  = (const float*)d_in[7];
    const int*   mmask  = (const int*)  d_in[8];
    const float* alpha  = (const float*)d_in[9];
    const float* beta   = (const float*)d_in[10];
    const float* var    = (const float*)d_in[11];
    const float* fs     = (const float*)d_in[12];
    const int*   iter   = (const int*)  d_in[13];
    const float* fe_w1  = (const float*)d_in[14];
    const float* fe_b1  = (const float*)d_in[15];
    const float* fe_w2  = (const float*)d_in[16];
    const float* fe_b2  = (const float*)d_in[17];
    const float* pr_w1  = (const float*)d_in[18];
    const float* pr_b1  = (const float*)d_in[19];
    const float* pr_w2  = (const float*)d_in[20];
    const float* pr_b2  = (const float*)d_in[21];
    const float* pr_w3  = (const float*)d_in[22];
    const float* pr_b3  = (const float*)d_in[23];
    const float* iw     = (const float*)d_in[24];
    float* d_out = (float*)d_out_v;

    fused_kernel<<<NGRID, NT>>>(s, eIF, xm, ym, sum_x, sum_y, lamuda, mmask,
                                initf, alpha, beta, var, fs, iter,
                                fe_w1, fe_b1, fe_w2, fe_b2,
                                pr_w1, pr_b1, pr_w2, pr_b2, pr_w3, pr_b3,
                                iw, d_out);
}